// round 16
// baseline (speedup 1.0000x reference)
#include <cuda_runtime.h>
#include <cuda_bf16.h>
#include <cstdint>

#define B_ROWS 2048
#define L_SEQ 50
#define EMBED 128
#define OUT_LD 50000
#define CUT0 12500
#define CUT1 25000
#define HEAD_N 12502
#define H0_DIM 64
#define H1_DIM 32
#define N_T1 25000
#define SSTRIDE 64

#define LOG2E 1.4426950408889634f

// ---------------- scratch (static device memory; no allocations) ----------------
__device__ __align__(16) __nv_bfloat16 g_pooled[B_ROWS * EMBED];
__device__ __align__(16) __nv_bfloat16 g_pooledS[B_ROWS * EMBED];   // * log2(e)
__device__ __align__(16) __nv_bfloat16 g_headw[HEAD_N * EMBED];
__device__ __align__(16) __nv_bfloat16 g_t0o[CUT0 * H0_DIM];
__device__ __align__(16) __nv_bfloat16 g_t1o[N_T1 * H1_DIM];
__device__ __align__(16) __nv_bfloat16 g_t0p[H0_DIM * EMBED];
__device__ __align__(16) __nv_bfloat16 g_t1p[H1_DIM * EMBED];
__device__ __align__(16) __nv_bfloat16 g_h0[B_ROWS * H0_DIM];
__device__ __align__(16) __nv_bfloat16 g_h0S[B_ROWS * H0_DIM];
__device__ __align__(16) __nv_bfloat16 g_h1[B_ROWS * H1_DIM];
__device__ __align__(16) __nv_bfloat16 g_h1S[B_ROWS * H1_DIM];
__device__ float g_stats_s[3 * B_ROWS * SSTRIDE];
__device__ float g_adds[B_ROWS * 3];

__device__ __forceinline__ uint32_t smem_u32(const void* p) {
    return (uint32_t)__cvta_generic_to_shared(p);
}
__device__ __forceinline__ float ex2f(float x) {
    float r; asm("ex2.approx.f32 %0, %1;" : "=f"(r) : "f"(x)); return r;
}
__device__ __forceinline__ float2 addf2(float2 a, float2 b) {
    union U { float2 f; unsigned long long u; } ua, ub, ur;
    ua.f = a; ub.f = b;
    asm("add.rn.f32x2 %0, %1, %2;" : "=l"(ur.u) : "l"(ua.u), "l"(ub.u));
    return ur.f;
}
__device__ __forceinline__ void cp16(uint32_t dst, const void* src, int sz) {
    asm volatile("cp.async.cg.shared.global [%0], [%1], 16, %2;"
                 :: "r"(dst), "l"(src), "r"(sz) : "memory");
}
#define CP_COMMIT() asm volatile("cp.async.commit_group;" ::: "memory")
#define CP_WAIT(n)  asm volatile("cp.async.wait_group %0;" :: "n"(n) : "memory")

// ---------------- prep: pooling (blocks 0..1023) + weight cvt ----------------
#define POOL_BLOCKS 1024
#define CVT_BLOCKS 640
#define NV_H  400064u
#define NV_0  200000u
#define NV_1  200000u
#define NV_P0 2048u
#define NV_P1 1024u
__global__ void __launch_bounds__(256)
prep_kernel(const int* __restrict__ x, const float* __restrict__ emb,
            const float* __restrict__ wh, const float* __restrict__ w0,
            const float* __restrict__ w1, const float* __restrict__ p0,
            const float* __restrict__ p1) {
    int tid = threadIdx.x;
    if (blockIdx.x < POOL_BLOCKS) {
        __shared__ int xs[2 * L_SEQ];
        int base = blockIdx.x * 2;
        if (tid < 2 * L_SEQ) xs[tid] = x[base * L_SEQ + tid];
        __syncthreads();
        int row = tid >> 7;
        int dim = tid & 127;
        float acc = 0.f; int cnt = 0;
        #pragma unroll
        for (int l = 0; l < L_SEQ; l++) {
            int idx = xs[row * L_SEQ + l];
            if (idx != 0) { cnt++; acc += emb[(size_t)idx * EMBED + dim]; }
        }
        float c = (float)(cnt < 1 ? 1 : cnt);
        float v = acc / c;
        int b = base + row;
        g_pooled[b * EMBED + dim] = __float2bfloat16(v);
        g_pooledS[b * EMBED + dim] = __float2bfloat16(v * LOG2E);
    } else {
        const unsigned total = NV_H + NV_0 + NV_1 + NV_P0 + NV_P1;
        for (unsigned i = (blockIdx.x - POOL_BLOCKS) * 256u + tid; i < total;
             i += CVT_BLOCKS * 256u) {
            const float* src; __nv_bfloat16* dst; unsigned j = i;
            if (j < NV_H) { src = wh; dst = g_headw; }
            else if ((j -= NV_H) < NV_0) { src = w0; dst = g_t0o; }
            else if ((j -= NV_0) < NV_1) { src = w1; dst = g_t1o; }
            else if ((j -= NV_1) < NV_P0) { src = p0; dst = g_t0p; }
            else { j -= NV_P0; src = p1; dst = g_t1p; }
            float4 v = reinterpret_cast<const float4*>(src)[j];
            __nv_bfloat162 lo = __float22bfloat162_rn(make_float2(v.x, v.y));
            __nv_bfloat162 hi = __float22bfloat162_rn(make_float2(v.z, v.w));
            uint2 pk;
            pk.x = *reinterpret_cast<uint32_t*>(&lo);
            pk.y = *reinterpret_cast<uint32_t*>(&hi);
            reinterpret_cast<uint2*>(dst)[j] = pk;
        }
    }
}

// ---------------- stats GEMM: register-accumulated sum-exp over NSUB subtiles ----------------
template <int K, int NSUB>
__device__ __forceinline__ void gemm_stats(
    const __nv_bfloat16* __restrict__ A, const __nv_bfloat16* __restrict__ W,
    int NW, int group, int m0, int n0base, int bxLocal, __nv_bfloat16* smem) {
    constexpr int TS = K + 8;
    constexpr int CW = K >> 3;
    __nv_bfloat16* As = smem;
    __nv_bfloat16* W0 = smem + 128 * TS;
    const int WBUF_BYTES = 64 * TS * 2;
    __shared__ float red_s[128][2];

    int tid = threadIdx.x;
    #pragma unroll
    for (int i = tid; i < 128 * CW; i += 256) {
        int r = i / CW, c = i - r * CW;
        cp16(smem_u32(As + r * TS + c * 8), A + (size_t)(m0 + r) * K + c * 8, 16);
    }
    #pragma unroll
    for (int i = tid; i < 64 * CW; i += 256) {
        int r = i / CW, c = i - r * CW;
        int wr = n0base + r;
        int wrc = wr < NW ? wr : (NW - 1);
        cp16(smem_u32(W0 + r * TS + c * 8), W + (size_t)wrc * K + c * 8, wr < NW ? 16 : 0);
    }
    CP_COMMIT();

    int warp = tid >> 5, lane = tid & 31;
    int g = lane >> 2, t4 = lane & 3;
    int wmi = warp >> 1;
    int wni = warp & 1;

    uint32_t aBase[2], bBase0[2];
    #pragma unroll
    for (int mt = 0; mt < 2; mt++)
        aBase[mt] = smem_u32(As + (wmi * 32 + mt * 16 + (lane & 15)) * TS + (lane >> 4) * 8);
    {
        int q = lane >> 3;
        int brow = (q >> 1) * 8 + (lane & 7);
        int bk = (q & 1) * 8;
        #pragma unroll
        for (int p = 0; p < 2; p++)
            bBase0[p] = smem_u32(W0 + (wni * 32 + p * 16 + brow) * TS + bk);
    }

    float rsum[2][2] = {{0.f, 0.f}, {0.f, 0.f}};

    #pragma unroll
    for (int s = 0; s < NSUB; s++) {
        int n0 = n0base + s * 64;
        if (n0 >= NW) break;
        bool havenext = (s + 1 < NSUB) && (n0base + (s + 1) * 64 < NW);
        if (havenext) {
            int n1 = n0 + 64;
            __nv_bfloat16* wb = W0 + ((s + 1) & 1) * (64 * TS);
            #pragma unroll
            for (int i = tid; i < 64 * CW; i += 256) {
                int r = i / CW, c = i - r * CW;
                int wr = n1 + r;
                int wrc = wr < NW ? wr : (NW - 1);
                cp16(smem_u32(wb + r * TS + c * 8),
                     W + (size_t)wrc * K + c * 8, wr < NW ? 16 : 0);
            }
            CP_COMMIT();
            CP_WAIT(1);
        } else {
            CP_WAIT(0);
        }
        __syncthreads();

        uint32_t bOff = (uint32_t)((s & 1) * WBUF_BYTES);
        float acc[2][4][4];
        #pragma unroll
        for (int mt = 0; mt < 2; mt++)
            #pragma unroll
            for (int nt = 0; nt < 4; nt++)
                #pragma unroll
                for (int i = 0; i < 4; i++) acc[mt][nt][i] = 0.f;

        #pragma unroll
        for (int k0 = 0; k0 < K; k0 += 16) {
            uint32_t a[2][4], b[2][4];
            #pragma unroll
            for (int mt = 0; mt < 2; mt++)
                asm volatile("ldmatrix.sync.aligned.m8n8.x4.shared.b16 {%0,%1,%2,%3}, [%4];"
                             : "=r"(a[mt][0]), "=r"(a[mt][1]), "=r"(a[mt][2]), "=r"(a[mt][3])
                             : "r"(aBase[mt] + k0 * 2));
            #pragma unroll
            for (int p = 0; p < 2; p++)
                asm volatile("ldmatrix.sync.aligned.m8n8.x4.shared.b16 {%0,%1,%2,%3}, [%4];"
                             : "=r"(b[p][0]), "=r"(b[p][1]), "=r"(b[p][2]), "=r"(b[p][3])
                             : "r"(bBase0[p] + bOff + k0 * 2));
            #pragma unroll
            for (int mt = 0; mt < 2; mt++)
                #pragma unroll
                for (int nt = 0; nt < 4; nt++) {
                    const uint32_t* bb = &b[nt >> 1][(nt & 1) * 2];
                    asm volatile(
                        "mma.sync.aligned.m16n8k16.row.col.f32.bf16.bf16.f32 "
                        "{%0,%1,%2,%3}, {%4,%5,%6,%7}, {%8,%9}, {%0,%1,%2,%3};"
                        : "+f"(acc[mt][nt][0]), "+f"(acc[mt][nt][1]),
                          "+f"(acc[mt][nt][2]), "+f"(acc[mt][nt][3])
                        : "r"(a[mt][0]), "r"(a[mt][1]), "r"(a[mt][2]), "r"(a[mt][3]),
                          "r"(bb[0]), "r"(bb[1]));
                }
        }

        bool full = (n0 + 64 <= NW);
        if (full) {
            #pragma unroll
            for (int mt = 0; mt < 2; mt++)
                #pragma unroll
                for (int half = 0; half < 2; half++) {
                    float ss = rsum[mt][half];
                    #pragma unroll
                    for (int nt = 0; nt < 4; nt++) {
                        ss += ex2f(acc[mt][nt][half * 2 + 0]);
                        ss += ex2f(acc[mt][nt][half * 2 + 1]);
                    }
                    rsum[mt][half] = ss;
                }
        } else {
            #pragma unroll
            for (int mt = 0; mt < 2; mt++)
                #pragma unroll
                for (int half = 0; half < 2; half++) {
                    float ss = rsum[mt][half];
                    #pragma unroll
                    for (int nt = 0; nt < 4; nt++)
                        #pragma unroll
                        for (int h = 0; h < 2; h++) {
                            int gc = n0 + wni * 32 + nt * 8 + t4 * 2 + h;
                            if (gc < NW) ss += ex2f(acc[mt][nt][half * 2 + h]);
                        }
                    rsum[mt][half] = ss;
                }
        }
        if (havenext) __syncthreads();
    }

    #pragma unroll
    for (int mt = 0; mt < 2; mt++)
        #pragma unroll
        for (int half = 0; half < 2; half++) {
            float ss = rsum[mt][half];
            ss += __shfl_xor_sync(0xffffffffu, ss, 1);
            ss += __shfl_xor_sync(0xffffffffu, ss, 2);
            if (t4 == 0) red_s[wmi * 32 + mt * 16 + g + half * 8][wni] = ss;
        }
    __syncthreads();
    if (tid < 128) {
        float S = red_s[tid][0] + red_s[tid][1];
        g_stats_s[((size_t)group * B_ROWS + m0 + tid) * SSTRIDE + bxLocal] = S;
    }
}

// ---------------- bf16 GEMM body, M-tile templated (proj MODE 0 / store MODE 2) ----------------
// MR = CTA M rows (64 or 128). 8 warps: 4 m-slices of MR/4 rows x 2 n-slices of 32 cols.
template <int K, int MODE, int NSUB, int MR>
__device__ __forceinline__ void gemm_multi(
    const __nv_bfloat16* __restrict__ A, const __nv_bfloat16* __restrict__ W,
    int NW, int NS, float* __restrict__ out, int colOff, int group,
    __nv_bfloat16* __restrict__ outBf, __nv_bfloat16* __restrict__ outBfS, int ldOutBf,
    int m0, int n0base, __nv_bfloat16* smem) {
    constexpr int TS = K + 8;
    constexpr int CW = K >> 3;
    constexpr int MT = MR / 64;          // m16 tiles per warp m-slice
    __nv_bfloat16* As = smem;            // [MR][TS]
    __nv_bfloat16* W0 = smem + MR * TS;  // 2x [64][TS]
    const int WBUF_BYTES = 64 * TS * 2;
    __shared__ float adds_s[MR];

    int tid = threadIdx.x;
    if (MODE == 2) {
        if (tid < MR) adds_s[tid] = g_adds[(m0 + tid) * 3 + group];
    }

    #pragma unroll
    for (int i = tid; i < MR * CW; i += 256) {
        int r = i / CW, c = i - r * CW;
        cp16(smem_u32(As + r * TS + c * 8), A + (size_t)(m0 + r) * K + c * 8, 16);
    }
    #pragma unroll
    for (int i = tid; i < 64 * CW; i += 256) {
        int r = i / CW, c = i - r * CW;
        int wr = n0base + r;
        int wrc = wr < NW ? wr : (NW - 1);
        cp16(smem_u32(W0 + r * TS + c * 8), W + (size_t)wrc * K + c * 8, wr < NW ? 16 : 0);
    }
    CP_COMMIT();

    int warp = tid >> 5, lane = tid & 31;
    int g = lane >> 2, t4 = lane & 3;
    int wmi = warp >> 1;
    int wni = warp & 1;

    uint32_t aBase[MT], bBase0[2];
    #pragma unroll
    for (int mt = 0; mt < MT; mt++)
        aBase[mt] = smem_u32(As + (wmi * (MT * 16) + mt * 16 + (lane & 15)) * TS + (lane >> 4) * 8);
    {
        int q = lane >> 3;
        int brow = (q >> 1) * 8 + (lane & 7);
        int bk = (q & 1) * 8;
        #pragma unroll
        for (int p = 0; p < 2; p++)
            bBase0[p] = smem_u32(W0 + (wni * 32 + p * 16 + brow) * TS + bk);
    }

    #pragma unroll
    for (int s = 0; s < NSUB; s++) {
        int n0 = n0base + s * 64;
        if (NSUB > 1 && n0 >= NW) break;
        bool havenext = false;
        if (s + 1 < NSUB && n0base + (s + 1) * 64 < NW) {
            havenext = true;
            int n1 = n0 + 64;
            __nv_bfloat16* wb = W0 + ((s + 1) & 1) * (64 * TS);
            #pragma unroll
            for (int i = tid; i < 64 * CW; i += 256) {
                int r = i / CW, c = i - r * CW;
                int wr = n1 + r;
                int wrc = wr < NW ? wr : (NW - 1);
                cp16(smem_u32(wb + r * TS + c * 8),
                     W + (size_t)wrc * K + c * 8, wr < NW ? 16 : 0);
            }
            CP_COMMIT();
            CP_WAIT(1);
        } else {
            CP_WAIT(0);
        }
        __syncthreads();

        uint32_t bOff = (uint32_t)((s & 1) * WBUF_BYTES);
        float acc[MT][4][4];
        #pragma unroll
        for (int mt = 0; mt < MT; mt++)
            #pragma unroll
            for (int nt = 0; nt < 4; nt++)
                #pragma unroll
                for (int i = 0; i < 4; i++) acc[mt][nt][i] = 0.f;

        #pragma unroll
        for (int k0 = 0; k0 < K; k0 += 16) {
            uint32_t a[MT][4], b[2][4];
            #pragma unroll
            for (int mt = 0; mt < MT; mt++)
                asm volatile("ldmatrix.sync.aligned.m8n8.x4.shared.b16 {%0,%1,%2,%3}, [%4];"
                             : "=r"(a[mt][0]), "=r"(a[mt][1]), "=r"(a[mt][2]), "=r"(a[mt][3])
                             : "r"(aBase[mt] + k0 * 2));
            #pragma unroll
            for (int p = 0; p < 2; p++)
                asm volatile("ldmatrix.sync.aligned.m8n8.x4.shared.b16 {%0,%1,%2,%3}, [%4];"
                             : "=r"(b[p][0]), "=r"(b[p][1]), "=r"(b[p][2]), "=r"(b[p][3])
                             : "r"(bBase0[p] + bOff + k0 * 2));
            #pragma unroll
            for (int mt = 0; mt < MT; mt++)
                #pragma unroll
                for (int nt = 0; nt < 4; nt++) {
                    const uint32_t* bb = &b[nt >> 1][(nt & 1) * 2];
                    asm volatile(
                        "mma.sync.aligned.m16n8k16.row.col.f32.bf16.bf16.f32 "
                        "{%0,%1,%2,%3}, {%4,%5,%6,%7}, {%8,%9}, {%0,%1,%2,%3};"
                        : "+f"(acc[mt][nt][0]), "+f"(acc[mt][nt][1]),
                          "+f"(acc[mt][nt][2]), "+f"(acc[mt][nt][3])
                        : "r"(a[mt][0]), "r"(a[mt][1]), "r"(a[mt][2]), "r"(a[mt][3]),
                          "r"(bb[0]), "r"(bb[1]));
                }
        }

        if (MODE == 0) {
            #pragma unroll
            for (int mt = 0; mt < MT; mt++)
                #pragma unroll
                for (int half = 0; half < 2; half++) {
                    int gr = m0 + wmi * (MT * 16) + mt * 16 + g + half * 8;
                    #pragma unroll
                    for (int nt = 0; nt < 4; nt++)
                        #pragma unroll
                        for (int h = 0; h < 2; h++) {
                            int gc = n0 + wni * 32 + nt * 8 + t4 * 2 + h;
                            if (gc < NW) {
                                float v = acc[mt][nt][half * 2 + h];
                                outBf[(size_t)gr * ldOutBf + gc] = __float2bfloat16(v);
                                outBfS[(size_t)gr * ldOutBf + gc] = __float2bfloat16(v * LOG2E);
                            }
                        }
                }
        } else {
            bool full = (n0 + 64 <= NS);
            #pragma unroll
            for (int mt = 0; mt < MT; mt++)
                #pragma unroll
                for (int half = 0; half < 2; half++) {
                    int rowRel = wmi * (MT * 16) + mt * 16 + g + half * 8;
                    size_t gr = (size_t)(m0 + rowRel);
                    float add = adds_s[rowRel];
                    float2 addv = make_float2(add, add);
                    float* rowp = out + gr * OUT_LD + colOff;
                    if (full) {
                        #pragma unroll
                        for (int nt = 0; nt < 4; nt++) {
                            int gc = n0 + wni * 32 + nt * 8 + t4 * 2;
                            float2 w = addf2(make_float2(acc[mt][nt][half * 2 + 0],
                                                         acc[mt][nt][half * 2 + 1]), addv);
                            __stcs(reinterpret_cast<float2*>(rowp + gc), w);
                        }
                    } else {
                        #pragma unroll
                        for (int nt = 0; nt < 4; nt++) {
                            int gc = n0 + wni * 32 + nt * 8 + t4 * 2;
                            if (gc < NS) {
                                float2 w = addf2(make_float2(acc[mt][nt][half * 2 + 0],
                                                             acc[mt][nt][half * 2 + 1]), addv);
                                __stcs(reinterpret_cast<float2*>(rowp + gc), w);
                            }
                        }
                    }
                }
            if (havenext) __syncthreads();
        }
    }
}

// ---------------- kernels ----------------
__global__ void __launch_bounds__(256, 3)
proj_kernel() {
    extern __shared__ __nv_bfloat16 sm[];
    int m0 = blockIdx.y * 128;
    if (blockIdx.x == 0)
        gemm_multi<128, 0, 1, 128>(g_pooled, g_t0p, H0_DIM, 0, nullptr, 0, 0,
                                   g_h0, g_h0S, H0_DIM, m0, 0, sm);
    else
        gemm_multi<128, 0, 1, 128>(g_pooled, g_t1p, H1_DIM, 0, nullptr, 0, 0,
                                   g_h1, g_h1S, H1_DIM, m0, 0, sm);
}

__global__ void __launch_bounds__(256, 3)
stats_kernel() {
    extern __shared__ __nv_bfloat16 sm[];
    int bx = blockIdx.x, m0 = blockIdx.y * 128;
    if (bx < 25)
        gemm_stats<128, 8>(g_pooledS, g_headw, HEAD_N, 0, m0, bx * 512, bx, sm);
    else if (bx < 50)
        gemm_stats<64, 8>(g_h0S, g_t0o, CUT0, 1, m0, (bx - 25) * 512, bx - 25, sm);
    else
        gemm_stats<32, 16>(g_h1S, g_t1o, N_T1, 2, m0, (bx - 50) * 1024, bx - 50, sm);
}

// store: M-tile 64, 4 CTAs/SM. grid (294, 32)
__global__ void __launch_bounds__(256, 4)
store_kernel(float* __restrict__ out) {
    extern __shared__ __nv_bfloat16 sm[];
    int bx = blockIdx.x, m0 = blockIdx.y * 64;
    if (bx < 98)
        gemm_multi<128, 2, 2, 64>(g_pooled, g_headw, HEAD_N, CUT0, out, 0, 0,
                                  nullptr, nullptr, 0, m0, bx * 128, sm);
    else if (bx < 196)
        gemm_multi<64, 2, 2, 64>(g_h0, g_t0o, CUT0, CUT0, out, CUT0, 1,
                                 nullptr, nullptr, 0, m0, (bx - 98) * 128, sm);
    else
        gemm_multi<32, 2, 4, 64>(g_h1, g_t1o, N_T1, N_T1, out, CUT1, 2,
                                 nullptr, nullptr, 0, m0, (bx - 196) * 256, sm);
}

// ---------------- combine: compact stats -> per-row adds (+ exact head extras) ----------------
__global__ void __launch_bounds__(256)
combine_kernel(const float* __restrict__ head_w_f) {
    int r = blockIdx.x * 8 + (threadIdx.x >> 5);
    int lane = threadIdx.x & 31;
    const float* p0 = g_stats_s + (size_t)r * SSTRIDE;
    const float* p1 = g_stats_s + ((size_t)B_ROWS + r) * SSTRIDE;
    const float* p2 = g_stats_s + ((size_t)2 * B_ROWS + r) * SSTRIDE;
    float s0 = (lane < 25) ? p0[lane] : 0.f;
    float s1 = (lane < 25) ? p1[lane] : 0.f;
    float s2 = p2[lane] + ((lane < 17) ? p2[32 + lane] : 0.f);

    uint2 pp = *reinterpret_cast<const uint2*>(g_pooled + r * EMBED + lane * 4);
    __nv_bfloat162 plo = *reinterpret_cast<__nv_bfloat162*>(&pp.x);
    __nv_bfloat162 phi = *reinterpret_cast<__nv_bfloat162*>(&pp.y);
    float f0 = __bfloat162float(plo.x), f1 = __bfloat162float(plo.y);
    float f2 = __bfloat162float(phi.x), f3 = __bfloat162float(phi.y);
    const float* w0r = head_w_f + (size_t)CUT0 * EMBED;
    float4 wa = *reinterpret_cast<const float4*>(w0r + lane * 4);
    float4 wb = *reinterpret_cast<const float4*>(w0r + EMBED + lane * 4);
    float e0 = f0 * wa.x + f1 * wa.y + f2 * wa.z + f3 * wa.w;
    float e1 = f0 * wb.x + f1 * wb.y + f2 * wb.z + f3 * wb.w;

    #pragma unroll
    for (int off = 16; off > 0; off >>= 1) {
        s0 += __shfl_xor_sync(0xffffffffu, s0, off);
        s1 += __shfl_xor_sync(0xffffffffu, s1, off);
        s2 += __shfl_xor_sync(0xffffffffu, s2, off);
        e0 += __shfl_xor_sync(0xffffffffu, e0, off);
        e1 += __shfl_xor_sync(0xffffffffu, e1, off);
    }
    if (lane == 0) {
        float l0 = logf(s0), l1 = logf(s1), l2 = logf(s2);
        g_adds[r * 3 + 0] = -l0;
        g_adds[r * 3 + 1] = e0 - l0 - l1;
        g_adds[r * 3 + 2] = e1 - l0 - l2;
    }
}

// ---------------- launch ----------------
extern "C" void kernel_launch(void* const* d_in, const int* in_sizes, int n_in,
                              void* d_out, int out_size) {
    const int*   x        = (const int*)d_in[0];
    const float* emb      = (const float*)d_in[1];
    const float* head_w_f = (const float*)d_in[2];
    const float* t0p_f    = (const float*)d_in[3];
    const float* t0o_f    = (const float*)d_in[4];
    const float* t1p_f    = (const float*)d_in[5];
    const float* t1o_f    = (const float*)d_in[6];
    float* out = (float*)d_out;

    const int SMB   = (128 + 128) * (128 + 8) * (int)sizeof(__nv_bfloat16);  // 69632
    const int SMB64 = (64 + 128) * (128 + 8) * (int)sizeof(__nv_bfloat16);   // 52224
    cudaFuncSetAttribute(stats_kernel, cudaFuncAttributeMaxDynamicSharedMemorySize, SMB);
    cudaFuncSetAttribute(store_kernel, cudaFuncAttributeMaxDynamicSharedMemorySize, SMB64);
    cudaFuncSetAttribute(proj_kernel, cudaFuncAttributeMaxDynamicSharedMemorySize, SMB);

    prep_kernel<<<POOL_BLOCKS + CVT_BLOCKS, 256>>>(x, emb, head_w_f, t0o_f, t1o_f,
                                                   t0p_f, t1p_f);
    proj_kernel<<<dim3(2, 16), 256, SMB>>>();
    stats_kernel<<<dim3(99, 16), 256, SMB>>>();
    combine_kernel<<<B_ROWS / 8, 256>>>(head_w_f);
    store_kernel<<<dim3(294, 32), 256, SMB64>>>(out);
}

// round 17
// speedup vs baseline: 1.0915x; 1.0915x over previous
#include <cuda_runtime.h>
#include <cuda_bf16.h>
#include <cstdint>

#define B_ROWS 2048
#define L_SEQ 50
#define EMBED 128
#define OUT_LD 50000
#define CUT0 12500
#define CUT1 25000
#define HEAD_N 12502
#define H0_DIM 64
#define H1_DIM 32
#define N_T1 25000
#define SSTRIDE 64

#define LOG2E 1.4426950408889634f

// ---------------- scratch (static device memory; no allocations) ----------------
__device__ __align__(16) __nv_bfloat16 g_pooled[B_ROWS * EMBED];
__device__ __align__(16) __nv_bfloat16 g_pooledS[B_ROWS * EMBED];   // * log2(e)
__device__ __align__(16) __nv_bfloat16 g_headw[HEAD_N * EMBED];
__device__ __align__(16) __nv_bfloat16 g_t0o[CUT0 * H0_DIM];
__device__ __align__(16) __nv_bfloat16 g_t1o[N_T1 * H1_DIM];
__device__ __align__(16) __nv_bfloat16 g_t0p[H0_DIM * EMBED];
__device__ __align__(16) __nv_bfloat16 g_t1p[H1_DIM * EMBED];
__device__ __align__(16) __nv_bfloat16 g_h0[B_ROWS * H0_DIM];
__device__ __align__(16) __nv_bfloat16 g_h0S[B_ROWS * H0_DIM];
__device__ __align__(16) __nv_bfloat16 g_h1[B_ROWS * H1_DIM];
__device__ __align__(16) __nv_bfloat16 g_h1S[B_ROWS * H1_DIM];
__device__ float g_stats_s[3 * B_ROWS * SSTRIDE];
__device__ float g_adds[B_ROWS * 3];

__device__ __forceinline__ uint32_t smem_u32(const void* p) {
    return (uint32_t)__cvta_generic_to_shared(p);
}
__device__ __forceinline__ float ex2f(float x) {
    float r; asm("ex2.approx.f32 %0, %1;" : "=f"(r) : "f"(x)); return r;
}
__device__ __forceinline__ float2 addf2(float2 a, float2 b) {
    union U { float2 f; unsigned long long u; } ua, ub, ur;
    ua.f = a; ub.f = b;
    asm("add.rn.f32x2 %0, %1, %2;" : "=l"(ur.u) : "l"(ua.u), "l"(ub.u));
    return ur.f;
}
__device__ __forceinline__ void cp16(uint32_t dst, const void* src, int sz) {
    asm volatile("cp.async.cg.shared.global [%0], [%1], 16, %2;"
                 :: "r"(dst), "l"(src), "r"(sz) : "memory");
}
#define CP_COMMIT() asm volatile("cp.async.commit_group;" ::: "memory")
#define CP_WAIT(n)  asm volatile("cp.async.wait_group %0;" :: "n"(n) : "memory")

// ---------------- prep: pooling (blocks 0..1023) + weight cvt ----------------
#define POOL_BLOCKS 1024
#define CVT_BLOCKS 640
#define NV_H  400064u
#define NV_0  200000u
#define NV_1  200000u
#define NV_P0 2048u
#define NV_P1 1024u
__global__ void __launch_bounds__(256)
prep_kernel(const int* __restrict__ x, const float* __restrict__ emb,
            const float* __restrict__ wh, const float* __restrict__ w0,
            const float* __restrict__ w1, const float* __restrict__ p0,
            const float* __restrict__ p1) {
    int tid = threadIdx.x;
    if (blockIdx.x < POOL_BLOCKS) {
        __shared__ int xs[2 * L_SEQ];
        int base = blockIdx.x * 2;
        if (tid < 2 * L_SEQ) xs[tid] = x[base * L_SEQ + tid];
        __syncthreads();
        int row = tid >> 7;
        int dim = tid & 127;
        float acc = 0.f; int cnt = 0;
        #pragma unroll
        for (int l = 0; l < L_SEQ; l++) {
            int idx = xs[row * L_SEQ + l];
            if (idx != 0) { cnt++; acc += emb[(size_t)idx * EMBED + dim]; }
        }
        float c = (float)(cnt < 1 ? 1 : cnt);
        float v = acc / c;
        int b = base + row;
        g_pooled[b * EMBED + dim] = __float2bfloat16(v);
        g_pooledS[b * EMBED + dim] = __float2bfloat16(v * LOG2E);
    } else {
        const unsigned total = NV_H + NV_0 + NV_1 + NV_P0 + NV_P1;
        for (unsigned i = (blockIdx.x - POOL_BLOCKS) * 256u + tid; i < total;
             i += CVT_BLOCKS * 256u) {
            const float* src; __nv_bfloat16* dst; unsigned j = i;
            if (j < NV_H) { src = wh; dst = g_headw; }
            else if ((j -= NV_H) < NV_0) { src = w0; dst = g_t0o; }
            else if ((j -= NV_0) < NV_1) { src = w1; dst = g_t1o; }
            else if ((j -= NV_1) < NV_P0) { src = p0; dst = g_t0p; }
            else { j -= NV_P0; src = p1; dst = g_t1p; }
            float4 v = reinterpret_cast<const float4*>(src)[j];
            __nv_bfloat162 lo = __float22bfloat162_rn(make_float2(v.x, v.y));
            __nv_bfloat162 hi = __float22bfloat162_rn(make_float2(v.z, v.w));
            uint2 pk;
            pk.x = *reinterpret_cast<uint32_t*>(&lo);
            pk.y = *reinterpret_cast<uint32_t*>(&hi);
            reinterpret_cast<uint2*>(dst)[j] = pk;
        }
    }
}

// ---------------- stats GEMM: register-accumulated sum-exp over NSUB subtiles ----------------
template <int K, int NSUB>
__device__ __forceinline__ void gemm_stats(
    const __nv_bfloat16* __restrict__ A, const __nv_bfloat16* __restrict__ W,
    int NW, int group, int m0, int n0base, int bxLocal, __nv_bfloat16* smem) {
    constexpr int TS = K + 8;
    constexpr int CW = K >> 3;
    __nv_bfloat16* As = smem;
    __nv_bfloat16* W0 = smem + 128 * TS;
    const int WBUF_BYTES = 64 * TS * 2;
    __shared__ float red_s[128][2];

    int tid = threadIdx.x;
    #pragma unroll
    for (int i = tid; i < 128 * CW; i += 256) {
        int r = i / CW, c = i - r * CW;
        cp16(smem_u32(As + r * TS + c * 8), A + (size_t)(m0 + r) * K + c * 8, 16);
    }
    #pragma unroll
    for (int i = tid; i < 64 * CW; i += 256) {
        int r = i / CW, c = i - r * CW;
        int wr = n0base + r;
        int wrc = wr < NW ? wr : (NW - 1);
        cp16(smem_u32(W0 + r * TS + c * 8), W + (size_t)wrc * K + c * 8, wr < NW ? 16 : 0);
    }
    CP_COMMIT();

    int warp = tid >> 5, lane = tid & 31;
    int g = lane >> 2, t4 = lane & 3;
    int wmi = warp >> 1;
    int wni = warp & 1;

    uint32_t aBase[2], bBase0[2];
    #pragma unroll
    for (int mt = 0; mt < 2; mt++)
        aBase[mt] = smem_u32(As + (wmi * 32 + mt * 16 + (lane & 15)) * TS + (lane >> 4) * 8);
    {
        int q = lane >> 3;
        int brow = (q >> 1) * 8 + (lane & 7);
        int bk = (q & 1) * 8;
        #pragma unroll
        for (int p = 0; p < 2; p++)
            bBase0[p] = smem_u32(W0 + (wni * 32 + p * 16 + brow) * TS + bk);
    }

    float rsum[2][2] = {{0.f, 0.f}, {0.f, 0.f}};

    #pragma unroll
    for (int s = 0; s < NSUB; s++) {
        int n0 = n0base + s * 64;
        if (n0 >= NW) break;
        bool havenext = (s + 1 < NSUB) && (n0base + (s + 1) * 64 < NW);
        if (havenext) {
            int n1 = n0 + 64;
            __nv_bfloat16* wb = W0 + ((s + 1) & 1) * (64 * TS);
            #pragma unroll
            for (int i = tid; i < 64 * CW; i += 256) {
                int r = i / CW, c = i - r * CW;
                int wr = n1 + r;
                int wrc = wr < NW ? wr : (NW - 1);
                cp16(smem_u32(wb + r * TS + c * 8),
                     W + (size_t)wrc * K + c * 8, wr < NW ? 16 : 0);
            }
            CP_COMMIT();
            CP_WAIT(1);
        } else {
            CP_WAIT(0);
        }
        __syncthreads();

        uint32_t bOff = (uint32_t)((s & 1) * WBUF_BYTES);
        float acc[2][4][4];
        #pragma unroll
        for (int mt = 0; mt < 2; mt++)
            #pragma unroll
            for (int nt = 0; nt < 4; nt++)
                #pragma unroll
                for (int i = 0; i < 4; i++) acc[mt][nt][i] = 0.f;

        #pragma unroll
        for (int k0 = 0; k0 < K; k0 += 16) {
            uint32_t a[2][4], b[2][4];
            #pragma unroll
            for (int mt = 0; mt < 2; mt++)
                asm volatile("ldmatrix.sync.aligned.m8n8.x4.shared.b16 {%0,%1,%2,%3}, [%4];"
                             : "=r"(a[mt][0]), "=r"(a[mt][1]), "=r"(a[mt][2]), "=r"(a[mt][3])
                             : "r"(aBase[mt] + k0 * 2));
            #pragma unroll
            for (int p = 0; p < 2; p++)
                asm volatile("ldmatrix.sync.aligned.m8n8.x4.shared.b16 {%0,%1,%2,%3}, [%4];"
                             : "=r"(b[p][0]), "=r"(b[p][1]), "=r"(b[p][2]), "=r"(b[p][3])
                             : "r"(bBase0[p] + bOff + k0 * 2));
            #pragma unroll
            for (int mt = 0; mt < 2; mt++)
                #pragma unroll
                for (int nt = 0; nt < 4; nt++) {
                    const uint32_t* bb = &b[nt >> 1][(nt & 1) * 2];
                    asm volatile(
                        "mma.sync.aligned.m16n8k16.row.col.f32.bf16.bf16.f32 "
                        "{%0,%1,%2,%3}, {%4,%5,%6,%7}, {%8,%9}, {%0,%1,%2,%3};"
                        : "+f"(acc[mt][nt][0]), "+f"(acc[mt][nt][1]),
                          "+f"(acc[mt][nt][2]), "+f"(acc[mt][nt][3])
                        : "r"(a[mt][0]), "r"(a[mt][1]), "r"(a[mt][2]), "r"(a[mt][3]),
                          "r"(bb[0]), "r"(bb[1]));
                }
        }

        bool full = (n0 + 64 <= NW);
        if (full) {
            #pragma unroll
            for (int mt = 0; mt < 2; mt++)
                #pragma unroll
                for (int half = 0; half < 2; half++) {
                    float ss = rsum[mt][half];
                    #pragma unroll
                    for (int nt = 0; nt < 4; nt++) {
                        ss += ex2f(acc[mt][nt][half * 2 + 0]);
                        ss += ex2f(acc[mt][nt][half * 2 + 1]);
                    }
                    rsum[mt][half] = ss;
                }
        } else {
            #pragma unroll
            for (int mt = 0; mt < 2; mt++)
                #pragma unroll
                for (int half = 0; half < 2; half++) {
                    float ss = rsum[mt][half];
                    #pragma unroll
                    for (int nt = 0; nt < 4; nt++)
                        #pragma unroll
                        for (int h = 0; h < 2; h++) {
                            int gc = n0 + wni * 32 + nt * 8 + t4 * 2 + h;
                            if (gc < NW) ss += ex2f(acc[mt][nt][half * 2 + h]);
                        }
                    rsum[mt][half] = ss;
                }
        }
        if (havenext) __syncthreads();
    }

    #pragma unroll
    for (int mt = 0; mt < 2; mt++)
        #pragma unroll
        for (int half = 0; half < 2; half++) {
            float ss = rsum[mt][half];
            ss += __shfl_xor_sync(0xffffffffu, ss, 1);
            ss += __shfl_xor_sync(0xffffffffu, ss, 2);
            if (t4 == 0) red_s[wmi * 32 + mt * 16 + g + half * 8][wni] = ss;
        }
    __syncthreads();
    if (tid < 128) {
        float S = red_s[tid][0] + red_s[tid][1];
        g_stats_s[((size_t)group * B_ROWS + m0 + tid) * SSTRIDE + bxLocal] = S;
    }
}

// ---------------- bf16 GEMM body, M-tile templated (proj MODE 0 / store MODE 2) ----------------
template <int K, int MODE, int NSUB, int MR>
__device__ __forceinline__ void gemm_multi(
    const __nv_bfloat16* __restrict__ A, const __nv_bfloat16* __restrict__ W,
    int NW, int NS, float* __restrict__ out, int colOff, int group,
    __nv_bfloat16* __restrict__ outBf, __nv_bfloat16* __restrict__ outBfS, int ldOutBf,
    int m0, int n0base, __nv_bfloat16* smem) {
    constexpr int TS = K + 8;
    constexpr int CW = K >> 3;
    constexpr int MT = MR / 64;
    __nv_bfloat16* As = smem;            // [MR][TS]
    __nv_bfloat16* W0 = smem + MR * TS;  // 2x [64][TS]
    const int WBUF_BYTES = 64 * TS * 2;
    __shared__ float adds_s[MR];

    int tid = threadIdx.x;
    if (MODE == 2) {
        if (tid < MR) adds_s[tid] = g_adds[(m0 + tid) * 3 + group];
    }

    #pragma unroll
    for (int i = tid; i < MR * CW; i += 256) {
        int r = i / CW, c = i - r * CW;
        cp16(smem_u32(As + r * TS + c * 8), A + (size_t)(m0 + r) * K + c * 8, 16);
    }
    #pragma unroll
    for (int i = tid; i < 64 * CW; i += 256) {
        int r = i / CW, c = i - r * CW;
        int wr = n0base + r;
        int wrc = wr < NW ? wr : (NW - 1);
        cp16(smem_u32(W0 + r * TS + c * 8), W + (size_t)wrc * K + c * 8, wr < NW ? 16 : 0);
    }
    CP_COMMIT();

    int warp = tid >> 5, lane = tid & 31;
    int g = lane >> 2, t4 = lane & 3;
    int wmi = warp >> 1;
    int wni = warp & 1;

    uint32_t aBase[MT], bBase0[2];
    #pragma unroll
    for (int mt = 0; mt < MT; mt++)
        aBase[mt] = smem_u32(As + (wmi * (MT * 16) + mt * 16 + (lane & 15)) * TS + (lane >> 4) * 8);
    {
        int q = lane >> 3;
        int brow = (q >> 1) * 8 + (lane & 7);
        int bk = (q & 1) * 8;
        #pragma unroll
        for (int p = 0; p < 2; p++)
            bBase0[p] = smem_u32(W0 + (wni * 32 + p * 16 + brow) * TS + bk);
    }

    #pragma unroll
    for (int s = 0; s < NSUB; s++) {
        int n0 = n0base + s * 64;
        if (NSUB > 1 && n0 >= NW) break;
        bool havenext = false;
        if (s + 1 < NSUB && n0base + (s + 1) * 64 < NW) {
            havenext = true;
            int n1 = n0 + 64;
            __nv_bfloat16* wb = W0 + ((s + 1) & 1) * (64 * TS);
            #pragma unroll
            for (int i = tid; i < 64 * CW; i += 256) {
                int r = i / CW, c = i - r * CW;
                int wr = n1 + r;
                int wrc = wr < NW ? wr : (NW - 1);
                cp16(smem_u32(wb + r * TS + c * 8),
                     W + (size_t)wrc * K + c * 8, wr < NW ? 16 : 0);
            }
            CP_COMMIT();
            CP_WAIT(1);
        } else {
            CP_WAIT(0);
        }
        __syncthreads();

        uint32_t bOff = (uint32_t)((s & 1) * WBUF_BYTES);
        float acc[MT][4][4];
        #pragma unroll
        for (int mt = 0; mt < MT; mt++)
            #pragma unroll
            for (int nt = 0; nt < 4; nt++)
                #pragma unroll
                for (int i = 0; i < 4; i++) acc[mt][nt][i] = 0.f;

        #pragma unroll
        for (int k0 = 0; k0 < K; k0 += 16) {
            uint32_t a[MT][4], b[2][4];
            #pragma unroll
            for (int mt = 0; mt < MT; mt++)
                asm volatile("ldmatrix.sync.aligned.m8n8.x4.shared.b16 {%0,%1,%2,%3}, [%4];"
                             : "=r"(a[mt][0]), "=r"(a[mt][1]), "=r"(a[mt][2]), "=r"(a[mt][3])
                             : "r"(aBase[mt] + k0 * 2));
            #pragma unroll
            for (int p = 0; p < 2; p++)
                asm volatile("ldmatrix.sync.aligned.m8n8.x4.shared.b16 {%0,%1,%2,%3}, [%4];"
                             : "=r"(b[p][0]), "=r"(b[p][1]), "=r"(b[p][2]), "=r"(b[p][3])
                             : "r"(bBase0[p] + bOff + k0 * 2));
            #pragma unroll
            for (int mt = 0; mt < MT; mt++)
                #pragma unroll
                for (int nt = 0; nt < 4; nt++) {
                    const uint32_t* bb = &b[nt >> 1][(nt & 1) * 2];
                    asm volatile(
                        "mma.sync.aligned.m16n8k16.row.col.f32.bf16.bf16.f32 "
                        "{%0,%1,%2,%3}, {%4,%5,%6,%7}, {%8,%9}, {%0,%1,%2,%3};"
                        : "+f"(acc[mt][nt][0]), "+f"(acc[mt][nt][1]),
                          "+f"(acc[mt][nt][2]), "+f"(acc[mt][nt][3])
                        : "r"(a[mt][0]), "r"(a[mt][1]), "r"(a[mt][2]), "r"(a[mt][3]),
                          "r"(bb[0]), "r"(bb[1]));
                }
        }

        if (MODE == 0) {
            #pragma unroll
            for (int mt = 0; mt < MT; mt++)
                #pragma unroll
                for (int half = 0; half < 2; half++) {
                    int gr = m0 + wmi * (MT * 16) + mt * 16 + g + half * 8;
                    #pragma unroll
                    for (int nt = 0; nt < 4; nt++)
                        #pragma unroll
                        for (int h = 0; h < 2; h++) {
                            int gc = n0 + wni * 32 + nt * 8 + t4 * 2 + h;
                            if (gc < NW) {
                                float v = acc[mt][nt][half * 2 + h];
                                outBf[(size_t)gr * ldOutBf + gc] = __float2bfloat16(v);
                                outBfS[(size_t)gr * ldOutBf + gc] = __float2bfloat16(v * LOG2E);
                            }
                        }
                }
        } else {
            bool full = (n0 + 64 <= NS);
            #pragma unroll
            for (int mt = 0; mt < MT; mt++)
                #pragma unroll
                for (int half = 0; half < 2; half++) {
                    int rowRel = wmi * (MT * 16) + mt * 16 + g + half * 8;
                    size_t gr = (size_t)(m0 + rowRel);
                    float add = adds_s[rowRel];
                    float2 addv = make_float2(add, add);
                    float* rowp = out + gr * OUT_LD + colOff;
                    if (full) {
                        #pragma unroll
                        for (int nt = 0; nt < 4; nt++) {
                            int gc = n0 + wni * 32 + nt * 8 + t4 * 2;
                            float2 w = addf2(make_float2(acc[mt][nt][half * 2 + 0],
                                                         acc[mt][nt][half * 2 + 1]), addv);
                            __stcs(reinterpret_cast<float2*>(rowp + gc), w);
                        }
                    } else {
                        #pragma unroll
                        for (int nt = 0; nt < 4; nt++) {
                            int gc = n0 + wni * 32 + nt * 8 + t4 * 2;
                            if (gc < NS) {
                                float2 w = addf2(make_float2(acc[mt][nt][half * 2 + 0],
                                                             acc[mt][nt][half * 2 + 1]), addv);
                                __stcs(reinterpret_cast<float2*>(rowp + gc), w);
                            }
                        }
                    }
                }
            if (havenext) __syncthreads();
        }
    }
}

// ---------------- kernels ----------------
// proj: M-tile 64 for 2x parallelism (64 blocks)
__global__ void __launch_bounds__(256, 4)
proj_kernel() {
    extern __shared__ __nv_bfloat16 sm[];
    int m0 = blockIdx.y * 64;
    if (blockIdx.x == 0)
        gemm_multi<128, 0, 1, 64>(g_pooled, g_t0p, H0_DIM, 0, nullptr, 0, 0,
                                  g_h0, g_h0S, H0_DIM, m0, 0, sm);
    else
        gemm_multi<128, 0, 1, 64>(g_pooled, g_t1p, H1_DIM, 0, nullptr, 0, 0,
                                  g_h1, g_h1S, H1_DIM, m0, 0, sm);
}

__global__ void __launch_bounds__(256, 3)
stats_kernel() {
    extern __shared__ __nv_bfloat16 sm[];
    int bx = blockIdx.x, m0 = blockIdx.y * 128;
    if (bx < 25)
        gemm_stats<128, 8>(g_pooledS, g_headw, HEAD_N, 0, m0, bx * 512, bx, sm);
    else if (bx < 50)
        gemm_stats<64, 8>(g_h0S, g_t0o, CUT0, 1, m0, (bx - 25) * 512, bx - 25, sm);
    else
        gemm_stats<32, 16>(g_h1S, g_t1o, N_T1, 2, m0, (bx - 50) * 1024, bx - 50, sm);
}

// store: R14 champion config (M=128, NSUB 2/2/4, grid 294x16)
__global__ void __launch_bounds__(256, 3)
store_kernel(float* __restrict__ out) {
    extern __shared__ __nv_bfloat16 sm[];
    int bx = blockIdx.x, m0 = blockIdx.y * 128;
    if (bx < 98)
        gemm_multi<128, 2, 2, 128>(g_pooled, g_headw, HEAD_N, CUT0, out, 0, 0,
                                   nullptr, nullptr, 0, m0, bx * 128, sm);
    else if (bx < 196)
        gemm_multi<64, 2, 2, 128>(g_h0, g_t0o, CUT0, CUT0, out, CUT0, 1,
                                  nullptr, nullptr, 0, m0, (bx - 98) * 128, sm);
    else
        gemm_multi<32, 2, 4, 128>(g_h1, g_t1o, N_T1, N_T1, out, CUT1, 2,
                                  nullptr, nullptr, 0, m0, (bx - 196) * 256, sm);
}

// ---------------- combine: compact stats -> per-row adds (+ exact head extras) ----------------
__global__ void __launch_bounds__(256)
combine_kernel(const float* __restrict__ head_w_f) {
    int r = blockIdx.x * 8 + (threadIdx.x >> 5);
    int lane = threadIdx.x & 31;
    const float* p0 = g_stats_s + (size_t)r * SSTRIDE;
    const float* p1 = g_stats_s + ((size_t)B_ROWS + r) * SSTRIDE;
    const float* p2 = g_stats_s + ((size_t)2 * B_ROWS + r) * SSTRIDE;
    float s0 = (lane < 25) ? p0[lane] : 0.f;
    float s1 = (lane < 25) ? p1[lane] : 0.f;
    float s2 = p2[lane] + ((lane < 17) ? p2[32 + lane] : 0.f);

    uint2 pp = *reinterpret_cast<const uint2*>(g_pooled + r * EMBED + lane * 4);
    __nv_bfloat162 plo = *reinterpret_cast<__nv_bfloat162*>(&pp.x);
    __nv_bfloat162 phi = *reinterpret_cast<__nv_bfloat162*>(&pp.y);
    float f0 = __bfloat162float(plo.x), f1 = __bfloat162float(plo.y);
    float f2 = __bfloat162float(phi.x), f3 = __bfloat162float(phi.y);
    const float* w0r = head_w_f + (size_t)CUT0 * EMBED;
    float4 wa = *reinterpret_cast<const float4*>(w0r + lane * 4);
    float4 wb = *reinterpret_cast<const float4*>(w0r + EMBED + lane * 4);
    float e0 = f0 * wa.x + f1 * wa.y + f2 * wa.z + f3 * wa.w;
    float e1 = f0 * wb.x + f1 * wb.y + f2 * wb.z + f3 * wb.w;

    #pragma unroll
    for (int off = 16; off > 0; off >>= 1) {
        s0 += __shfl_xor_sync(0xffffffffu, s0, off);
        s1 += __shfl_xor_sync(0xffffffffu, s1, off);
        s2 += __shfl_xor_sync(0xffffffffu, s2, off);
        e0 += __shfl_xor_sync(0xffffffffu, e0, off);
        e1 += __shfl_xor_sync(0xffffffffu, e1, off);
    }
    if (lane == 0) {
        float l0 = logf(s0), l1 = logf(s1), l2 = logf(s2);
        g_adds[r * 3 + 0] = -l0;
        g_adds[r * 3 + 1] = e0 - l0 - l1;
        g_adds[r * 3 + 2] = e1 - l0 - l2;
    }
}

// ---------------- launch ----------------
extern "C" void kernel_launch(void* const* d_in, const int* in_sizes, int n_in,
                              void* d_out, int out_size) {
    const int*   x        = (const int*)d_in[0];
    const float* emb      = (const float*)d_in[1];
    const float* head_w_f = (const float*)d_in[2];
    const float* t0p_f    = (const float*)d_in[3];
    const float* t0o_f    = (const float*)d_in[4];
    const float* t1p_f    = (const float*)d_in[5];
    const float* t1o_f    = (const float*)d_in[6];
    float* out = (float*)d_out;

    const int SMB   = (128 + 128) * (128 + 8) * (int)sizeof(__nv_bfloat16);  // 69632
    const int SMB64 = (64 + 128) * (128 + 8) * (int)sizeof(__nv_bfloat16);   // 52224
    cudaFuncSetAttribute(stats_kernel, cudaFuncAttributeMaxDynamicSharedMemorySize, SMB);
    cudaFuncSetAttribute(store_kernel, cudaFuncAttributeMaxDynamicSharedMemorySize, SMB);
    cudaFuncSetAttribute(proj_kernel, cudaFuncAttributeMaxDynamicSharedMemorySize, SMB64);

    prep_kernel<<<POOL_BLOCKS + CVT_BLOCKS, 256>>>(x, emb, head_w_f, t0o_f, t1o_f,
                                                   t0p_f, t1p_f);
    proj_kernel<<<dim3(2, 32), 256, SMB64>>>();
    stats_kernel<<<dim3(99, 16), 256, SMB>>>();
    combine_kernel<<<B_ROWS / 8, 256>>>(head_w_f);
    store_kernel<<<dim3(294, 16), 256, SMB>>>(out);
}